// round 3
// baseline (speedup 1.0000x reference)
#include <cuda_runtime.h>
#include <cuda_bf16.h>
#include <math.h>

#define Bb 4
#define Cc 192
#define Hh 64
#define Wd 64
#define Ll 4096
#define Dd 384
#define Nst 16
#define Rr 12
#define BLD (Bb*Ll*Dd)
#define NCH 16
#define CHL 256

typedef unsigned long long u64t;

__device__ __forceinline__ u64t pack2(float x){
    u64t r; asm("mov.b64 %0, {%1, %1};" : "=l"(r) : "f"(x)); return r;
}
__device__ __forceinline__ void ffma2(u64t &d, u64t a, u64t b){
    asm("fma.rn.f32x2 %0, %1, %2, %0;" : "+l"(d) : "l"(a), "l"(b));
}
__device__ __forceinline__ void unpack2(u64t v, float &lo, float &hi){
    asm("mov.b64 {%0, %1}, %2;" : "=f"(lo), "=f"(hi) : "l"(v));
}

// scratch
__device__ float g_part[2*128*Bb];
__device__ float g_sum[Bb], g_sumsq[Bb];
__device__ float g_u[BLD];      // snake order
__device__ float g_z[BLD];      // raster order
__device__ float g_uc[BLD];     // snake order
__device__ float g_delta[BLD];  // snake order
__device__ float g_yg[BLD];     // raster order (gated)
__device__ float g_y2[BLD];     // raster order (after LE)
__device__ float g_dt[Bb*Ll*Rr];
__device__ float g_Bm[Bb*Ll*Nst];
__device__ float g_Cm[Bb*Ll*Nst];
__device__ float g_wf[Cc*Dd];
__device__ float g_hend[Bb*NCH*Dd*Nst];
__device__ float g_aprod[Bb*NCH*Dd*Nst];
__device__ float g_hin[Bb*NCH*Dd*Nst];

// ---------------- GroupNorm stats ----------------
__global__ void k_gnstats(const float* __restrict__ x){
    int b = blockIdx.y;
    const float4* xb = (const float4*)(x + (size_t)b*Cc*Ll);
    const int nt = (Cc*Ll)/4;
    float s = 0.f, q = 0.f;
    for (int i = blockIdx.x*blockDim.x + threadIdx.x; i < nt; i += gridDim.x*blockDim.x){
        float4 v = xb[i];
        s += v.x + v.y + v.z + v.w;
        q += v.x*v.x + v.y*v.y + v.z*v.z + v.w*v.w;
    }
    __shared__ float ss[256], qq[256];
    int t = threadIdx.x;
    ss[t] = s; qq[t] = q; __syncthreads();
    for (int o = 128; o > 0; o >>= 1){
        if (t < o){ ss[t] += ss[t+o]; qq[t] += qq[t+o]; }
        __syncthreads();
    }
    if (t == 0){
        g_part[b*128 + blockIdx.x] = ss[0];
        g_part[512 + b*128 + blockIdx.x] = qq[0];
    }
}

__global__ void k_gnfin(){
    int b = blockIdx.x, t = threadIdx.x;
    __shared__ float ss[128], qq[128];
    ss[t] = g_part[b*128 + t];
    qq[t] = g_part[512 + b*128 + t];
    __syncthreads();
    for (int o = 64; o > 0; o >>= 1){
        if (t < o){ ss[t] += ss[t+o]; qq[t] += qq[t+o]; }
        __syncthreads();
    }
    if (t == 0){ g_sum[b] = ss[0]; g_sumsq[b] = qq[0]; }
}

// ---------------- fused final weight ----------------
__global__ void k_wfuse(const float* __restrict__ P, const float* __restrict__ Wo){
    int idx = blockIdx.x*256 + threadIdx.x;
    if (idx >= Cc*Dd) return;
    int o = idx / Dd, d = idx % Dd;
    float acc = 0.f;
    for (int c = 0; c < Cc; c++) acc = fmaf(P[o*Cc + c], Wo[c*Dd + d], acc);
    g_wf[idx] = acc;
}

// ---------------- GEMM1: GN + in_proj (128x128, 8x8/thread, FFMA2) --------
__global__ __launch_bounds__(256) void k_inproj(const float* __restrict__ x,
        const float* __restrict__ gamma, const float* __restrict__ beta,
        const float* __restrict__ W){
    const int b  = blockIdx.z;
    const int m0 = blockIdx.x*128;
    const int n0 = blockIdx.y*128;
    const int tid = threadIdx.x;
    const int tx = tid & 15, ty = tid >> 4;
    __shared__ float As[16][128];
    __shared__ float Bs[16][128];
    const float inv = 1.f/(float)(Cc*Ll);
    float mu   = g_sum[b]*inv;
    float var  = g_sumsq[b]*inv - mu*mu;
    float rstd = rsqrtf(var + 1e-5f);
    const float* xb = x + (size_t)b*Cc*Ll;
    u64t acc[8][4];
    #pragma unroll
    for (int i = 0; i < 8; i++)
        #pragma unroll
        for (int j = 0; j < 4; j++) acc[i][j] = 0ull;
    for (int k0 = 0; k0 < Cc; k0 += 16){
        #pragma unroll
        for (int i = 0; i < 2; i++){
            int lin = tid + i*256;
            int k = lin >> 5, m4 = lin & 31;
            float4 v = *(const float4*)&xb[(size_t)(k0+k)*Ll + m0 + m4*4];
            float g = gamma[k0+k]*rstd, bt = beta[k0+k] - mu*gamma[k0+k]*rstd;
            v.x = fmaf(v.x, g, bt); v.y = fmaf(v.y, g, bt);
            v.z = fmaf(v.z, g, bt); v.w = fmaf(v.w, g, bt);
            *(float4*)&As[k][m4*4] = v;
        }
        #pragma unroll
        for (int i = 0; i < 2; i++){
            int lin = tid + i*256;
            int n = lin & 127, kq = lin >> 7;
            float4 v = *(const float4*)&W[(size_t)(n0+n)*Cc + k0 + kq*4];
            Bs[kq*4+0][n] = v.x; Bs[kq*4+1][n] = v.y;
            Bs[kq*4+2][n] = v.z; Bs[kq*4+3][n] = v.w;
        }
        __syncthreads();
        #pragma unroll
        for (int kk = 0; kk < 16; kk++){
            float a[8];
            *(float4*)&a[0] = *(const float4*)&As[kk][ty*8];
            *(float4*)&a[4] = *(const float4*)&As[kk][ty*8+4];
            ulonglong2 bv0 = *(const ulonglong2*)&Bs[kk][tx*8];
            ulonglong2 bv1 = *(const ulonglong2*)&Bs[kk][tx*8+4];
            u64t b2[4] = {bv0.x, bv0.y, bv1.x, bv1.y};
            u64t a2[8];
            #pragma unroll
            for (int i = 0; i < 8; i++) a2[i] = pack2(a[i]);
            #pragma unroll
            for (int i = 0; i < 8; i++)
                #pragma unroll
                for (int j = 0; j < 4; j++)
                    ffma2(acc[i][j], a2[i], b2[j]);
        }
        __syncthreads();
    }
    #pragma unroll
    for (int i = 0; i < 8; i++){
        float f[8];
        #pragma unroll
        for (int j = 0; j < 4; j++) unpack2(acc[i][j], f[2*j], f[2*j+1]);
        int m = m0 + ty*8 + i;
        if (n0 < Dd){
            int hh = m >> 6, ww = m & 63;
            int lp = (hh & 1) ? ((hh << 6) + (63 - ww)) : m;
            float* p = &g_u[((size_t)b*Ll + lp)*Dd + n0 + tx*8];
            *(float4*)p     = make_float4(f[0],f[1],f[2],f[3]);
            *(float4*)(p+4) = make_float4(f[4],f[5],f[6],f[7]);
        } else {
            float* p = &g_z[((size_t)b*Ll + m)*Dd + (n0-Dd) + tx*8];
            *(float4*)p     = make_float4(f[0],f[1],f[2],f[3]);
            *(float4*)(p+4) = make_float4(f[4],f[5],f[6],f[7]);
        }
    }
}

// ---------------- causal depthwise conv1d + SiLU ----------------
__global__ void k_conv(const float* __restrict__ cw, const float* __restrict__ cb){
    int idx = blockIdx.x*256 + threadIdx.x;
    if (idx >= BLD) return;
    int d = idx % Dd; int bl = idx / Dd; int l = bl % Ll; int b = bl / Ll;
    float acc = cb[d];
    #pragma unroll
    for (int j = 0; j < 4; j++){
        int ls = l - 3 + j;
        if (ls >= 0) acc = fmaf(g_u[((size_t)b*Ll + ls)*Dd + d], cw[d*4 + j], acc);
    }
    g_uc[idx] = acc / (1.f + __expf(-acc));
}

// ---------------- GEMM2: dbl = u_c @ x_proj_w^T (FFMA2) ----------------
__global__ void k_dbl(const float* __restrict__ Wx){
    const int m0 = blockIdx.x*64;
    const int tid = threadIdx.x;
    const int tx = tid & 15, ty = tid >> 4;
    __shared__ float As[16][68];
    __shared__ float Bs[16][64];
    u64t acc[4][2] = {};
    for (int k0 = 0; k0 < Dd; k0 += 16){
        #pragma unroll
        for (int i = 0; i < 4; i++){
            int idx = tid + i*256;
            int m = idx >> 4, k = idx & 15;
            As[k][m] = g_uc[(size_t)(m0+m)*Dd + k0+k];
        }
        #pragma unroll
        for (int i = 0; i < 4; i++){
            int idx = tid + i*256;
            int n = idx >> 4, k = idx & 15;
            Bs[k][n] = (n < 44) ? Wx[(size_t)n*Dd + k0+k] : 0.f;
        }
        __syncthreads();
        #pragma unroll
        for (int kk = 0; kk < 16; kk++){
            float4 av = *(const float4*)&As[kk][ty*4];
            ulonglong2 bv = *(const ulonglong2*)&Bs[kk][tx*4];
            u64t b2[2] = {bv.x, bv.y};
            u64t a2[4] = {pack2(av.x), pack2(av.y), pack2(av.z), pack2(av.w)};
            #pragma unroll
            for (int i = 0; i < 4; i++)
                #pragma unroll
                for (int j = 0; j < 2; j++)
                    ffma2(acc[i][j], a2[i], b2[j]);
        }
        __syncthreads();
    }
    #pragma unroll
    for (int i = 0; i < 4; i++){
        float f[4];
        unpack2(acc[i][0], f[0], f[1]);
        unpack2(acc[i][1], f[2], f[3]);
        size_t row = m0 + ty*4 + i;
        #pragma unroll
        for (int j = 0; j < 4; j++){
            int e = tx*4 + j;
            if (e < 12)      g_dt[row*Rr + e]        = f[j];
            else if (e < 28) g_Bm[row*Nst + (e-12)]  = f[j];
            else if (e < 44) g_Cm[row*Nst + (e-28)]  = f[j];
        }
    }
}

// ---------------- delta = softplus(dt @ dt_proj_w^T + b) -------------------
__global__ void k_delta(const float* __restrict__ dtw, const float* __restrict__ dtb){
    __shared__ float sw[Dd*13];
    for (int i = threadIdx.x; i < Dd*Rr; i += 256){
        int d = i / Rr, r = i % Rr;
        sw[d*13 + r] = dtw[i];
    }
    __syncthreads();
    for (int idx = blockIdx.x*256 + threadIdx.x; idx < BLD; idx += gridDim.x*256){
        int d = idx % Dd; size_t row = idx / Dd;
        const float* dtr = g_dt + row*Rr;
        float acc = dtb[d];
        #pragma unroll
        for (int r = 0; r < Rr; r++) acc = fmaf(dtr[r], sw[d*13 + r], acc);
        g_delta[idx] = fmaxf(acc, 0.f) + __logf(1.f + __expf(-fabsf(acc)));
    }
}

// ---------------- scan pass A ----------------
__global__ void k_scanA(const float* __restrict__ Alog){
    const int b = blockIdx.z;
    const int ch = blockIdx.y;
    const int dBase = blockIdx.x*16;
    const int tid = threadIdx.x;
    const int dl = tid >> 4;
    const int n  = tid & 15;
    const int d  = dBase + dl;
    float An = -__expf(Alog[d*Nst + n]);
    __shared__ float s_d[64][16], s_u[64][16], s_B[64][16];
    float h = 0.f, S = 0.f;
    const size_t base = (size_t)b*Ll + (size_t)ch*CHL;
    const float* pD = g_delta + base*Dd + dBase;
    const float* pU = g_uc    + base*Dd + dBase;
    const float* pB = g_Bm    + base*Nst;
    for (int l0 = 0; l0 < CHL; l0 += 64){
        #pragma unroll
        for (int i = 0; i < 4; i++){
            int idx = tid + i*256;
            int t = idx >> 4, c = idx & 15;
            s_d[t][c] = pD[(size_t)(l0+t)*Dd + c];
            s_u[t][c] = pU[(size_t)(l0+t)*Dd + c];
            s_B[t][c] = pB[(size_t)(l0+t)*Nst + c];
        }
        __syncthreads();
        #pragma unroll 8
        for (int t = 0; t < 64; t++){
            float dv = s_d[t][dl];
            float dA = __expf(dv * An);
            h = fmaf(dA, h, (dv*s_u[t][dl]) * s_B[t][n]);
            S += dv;
        }
        __syncthreads();
    }
    size_t o = (((size_t)b*NCH + ch)*Dd + d)*Nst + n;
    g_hend[o]  = h;
    g_aprod[o] = __expf(An * S);
}

// ---------------- scan pass B ----------------
__global__ void k_scanB(){
    int gid = blockIdx.x*256 + threadIdx.x;
    int b = gid / (Dd*Nst);
    int rem = gid % (Dd*Nst);
    float hin = 0.f;
    #pragma unroll
    for (int c = 0; c < NCH; c++){
        size_t o = ((size_t)(b*NCH + c))*(Dd*Nst) + rem;
        g_hin[o] = hin;
        hin = g_aprod[o]*hin + g_hend[o];
    }
}

// ---------------- scan pass C (+ fused un-snake + gate) --------------------
__global__ void k_scanC(const float* __restrict__ Alog, const float* __restrict__ Dsk){
    const int b = blockIdx.z;
    const int ch = blockIdx.y;
    const int dBase = blockIdx.x*16;
    const int tid = threadIdx.x;
    const int dl = tid >> 4;
    const int n  = tid & 15;
    const int d  = dBase + dl;
    float An  = -__expf(Alog[d*Nst + n]);
    float dsk = Dsk[d];
    __shared__ float s_d[64][16], s_u[64][16], s_B[64][16], s_C[64][16];
    float h = g_hin[(((size_t)b*NCH + ch)*Dd + d)*Nst + n];
    const size_t base = (size_t)b*Ll + (size_t)ch*CHL;
    const float* pD = g_delta + base*Dd + dBase;
    const float* pU = g_uc    + base*Dd + dBase;
    const float* pB = g_Bm    + base*Nst;
    const float* pC = g_Cm    + base*Nst;
    for (int l0 = 0; l0 < CHL; l0 += 64){
        #pragma unroll
        for (int i = 0; i < 4; i++){
            int idx = tid + i*256;
            int t = idx >> 4, c = idx & 15;
            s_d[t][c] = pD[(size_t)(l0+t)*Dd + c];
            s_u[t][c] = pU[(size_t)(l0+t)*Dd + c];
            s_B[t][c] = pB[(size_t)(l0+t)*Nst + c];
            s_C[t][c] = pC[(size_t)(l0+t)*Nst + c];
        }
        __syncthreads();
        #pragma unroll 4
        for (int t = 0; t < 64; t++){
            float dv = s_d[t][dl];
            float uv = s_u[t][dl];
            float dA = __expf(dv * An);
            h = fmaf(dA, h, (dv*uv) * s_B[t][n]);
            float p = h * s_C[t][n];
            p += __shfl_xor_sync(0xffffffffu, p, 8);
            p += __shfl_xor_sync(0xffffffffu, p, 4);
            p += __shfl_xor_sync(0xffffffffu, p, 2);
            p += __shfl_xor_sync(0xffffffffu, p, 1);
            if (n == 0){
                int ls = ch*CHL + l0 + t;                 // snake index
                int hh = ls >> 6, ww = ls & 63;
                int lr = (hh & 1) ? ((hh << 6) + (63 - ww)) : ls;  // raster
                size_t zi = ((size_t)b*Ll + lr)*Dd + dl + dBase;
                float zv = g_z[zi];
                float yv = p + uv*dsk;
                g_yg[zi] = yv * (zv / (1.f + __expf(-zv)));
            }
        }
        __syncthreads();
    }
}

// ---------------- depthwise 3x3 + residual ----------------
__global__ void k_le(const float* __restrict__ lw){
    int idx = blockIdx.x*256 + threadIdx.x;
    if (idx >= BLD) return;
    int d = idx % Dd; int bl = idx / Dd; int l = bl % Ll; int b = bl / Ll;
    int hh = l >> 6, ww = l & 63;
    float acc = g_yg[idx];
    #pragma unroll
    for (int dh = -1; dh <= 1; dh++){
        int h2 = hh + dh;
        if ((unsigned)h2 >= (unsigned)Hh) continue;
        #pragma unroll
        for (int dw = -1; dw <= 1; dw++){
            int w2 = ww + dw;
            if ((unsigned)w2 >= (unsigned)Wd) continue;
            acc = fmaf(g_yg[((size_t)b*Ll + (h2<<6) + w2)*Dd + d],
                       lw[d*9 + (dh+1)*3 + (dw+1)], acc);
        }
    }
    g_y2[idx] = acc;
}

// ---------------- GEMM3: out (128x64, 8x4/thread, FFMA2) ----------------
__global__ __launch_bounds__(256) void k_out(float* __restrict__ out){
    const int m0 = blockIdx.x*128;
    const int n0 = blockIdx.y*64;
    const int tid = threadIdx.x;
    const int tx = tid & 15, ty = tid >> 4;
    __shared__ float As[16][128];
    __shared__ float Bs[16][64];
    u64t acc[8][2] = {};
    for (int k0 = 0; k0 < Dd; k0 += 16){
        #pragma unroll
        for (int i = 0; i < 2; i++){
            int lin = tid + i*256;
            int m = lin & 127, kq = lin >> 7;
            float4 v = *(const float4*)&g_y2[(size_t)(m0+m)*Dd + k0 + kq*4];
            As[kq*4+0][m] = v.x; As[kq*4+1][m] = v.y;
            As[kq*4+2][m] = v.z; As[kq*4+3][m] = v.w;
        }
        {
            int n = tid & 63, kq = tid >> 6;
            float4 v = *(const float4*)&g_wf[(size_t)(n0+n)*Dd + k0 + kq*4];
            Bs[kq*4+0][n] = v.x; Bs[kq*4+1][n] = v.y;
            Bs[kq*4+2][n] = v.z; Bs[kq*4+3][n] = v.w;
        }
        __syncthreads();
        #pragma unroll
        for (int kk = 0; kk < 16; kk++){
            float a[8];
            *(float4*)&a[0] = *(const float4*)&As[kk][ty*8];
            *(float4*)&a[4] = *(const float4*)&As[kk][ty*8+4];
            ulonglong2 bv = *(const ulonglong2*)&Bs[kk][tx*4];
            u64t b2[2] = {bv.x, bv.y};
            u64t a2[8];
            #pragma unroll
            for (int i = 0; i < 8; i++) a2[i] = pack2(a[i]);
            #pragma unroll
            for (int i = 0; i < 8; i++)
                #pragma unroll
                for (int j = 0; j < 2; j++)
                    ffma2(acc[i][j], a2[i], b2[j]);
        }
        __syncthreads();
    }
    int b = m0 >> 12;
    int lbase = (m0 & 4095) + ty*8;
    float f[8][4];
    #pragma unroll
    for (int i = 0; i < 8; i++){
        unpack2(acc[i][0], f[i][0], f[i][1]);
        unpack2(acc[i][1], f[i][2], f[i][3]);
    }
    #pragma unroll
    for (int j = 0; j < 4; j++){
        int o = n0 + tx*4 + j;
        float* p = &out[((size_t)b*Cc + o)*Ll + lbase];
        *(float4*)p     = make_float4(f[0][j], f[1][j], f[2][j], f[3][j]);
        *(float4*)(p+4) = make_float4(f[4][j], f[5][j], f[6][j], f[7][j]);
    }
}

extern "C" void kernel_launch(void* const* d_in, const int* in_sizes, int n_in,
                              void* d_out, int out_size){
    const float* x          = (const float*)d_in[0];
    const float* gn_gamma   = (const float*)d_in[1];
    const float* gn_beta    = (const float*)d_in[2];
    const float* in_proj_w  = (const float*)d_in[3];
    const float* conv1d_w   = (const float*)d_in[4];
    const float* conv1d_b   = (const float*)d_in[5];
    const float* x_proj_w   = (const float*)d_in[6];
    const float* dt_proj_w  = (const float*)d_in[7];
    const float* dt_proj_b  = (const float*)d_in[8];
    const float* A_log      = (const float*)d_in[9];
    const float* Dskip      = (const float*)d_in[10];
    const float* le_w       = (const float*)d_in[11];
    const float* out_proj_w = (const float*)d_in[12];
    const float* proj_out_w = (const float*)d_in[13];
    float* out = (float*)d_out;

    k_gnstats<<<dim3(128, Bb), 256>>>(x);
    k_gnfin<<<Bb, 128>>>();
    k_wfuse<<<(Cc*Dd + 255)/256, 256>>>(proj_out_w, out_proj_w);
    k_inproj<<<dim3(Ll/128, 768/128, Bb), 256>>>(x, gn_gamma, gn_beta, in_proj_w);
    k_conv<<<BLD/256, 256>>>(conv1d_w, conv1d_b);
    k_dbl<<<(Bb*Ll)/64, 256>>>(x_proj_w);
    k_delta<<<2048, 256>>>(dt_proj_w, dt_proj_b);
    k_scanA<<<dim3(Dd/16, NCH, Bb), 256>>>(A_log);
    k_scanB<<<(Bb*Dd*Nst)/256, 256>>>();
    k_scanC<<<dim3(Dd/16, NCH, Bb), 256>>>(A_log, Dskip);
    k_le<<<BLD/256, 256>>>(le_w);
    k_out<<<dim3((Bb*Ll)/128, Cc/64), 256>>>(out);
}

// round 4
// speedup vs baseline: 1.6396x; 1.6396x over previous
#include <cuda_runtime.h>
#include <cuda_bf16.h>
#include <math.h>

#define Bb 4
#define Cc 192
#define Hh 64
#define Wd 64
#define Ll 4096
#define Dd 384
#define Nst 16
#define Rr 12
#define BLD (Bb*Ll*Dd)
#define NCH 16
#define CHL 256

// scratch
__device__ float g_part[2*128*Bb];
__device__ float g_sum[Bb], g_sumsq[Bb];
__device__ float g_u[BLD];      // snake order
__device__ float g_z[BLD];      // raster order
__device__ float g_uc[BLD];     // snake order
__device__ float g_delta[BLD];  // snake order
__device__ float g_y[BLD];      // snake order
__device__ float g_yg[BLD];     // raster order
__device__ float g_y2[BLD];     // raster order
__device__ float g_dt[Bb*Ll*Rr];
__device__ float g_Bm[Bb*Ll*Nst];
__device__ float g_Cm[Bb*Ll*Nst];
__device__ float g_wf[Cc*Dd];
__device__ float g_hend[Bb*NCH*Dd*Nst];
__device__ float g_aprod[Bb*NCH*Dd*Nst];
__device__ float g_hin[Bb*NCH*Dd*Nst];

__device__ __forceinline__ unsigned cvt_tf32(float v){
    unsigned r; asm("cvt.rna.tf32.f32 %0, %1;" : "=r"(r) : "f"(v)); return r;
}
__device__ __forceinline__ void mma_tf32(float &d0, float &d1, float &d2, float &d3,
        unsigned a0, unsigned a1, unsigned a2, unsigned a3, unsigned b0, unsigned b1){
    asm("mma.sync.aligned.m16n8k8.row.col.f32.tf32.tf32.f32 "
        "{%0,%1,%2,%3}, {%4,%5,%6,%7}, {%8,%9}, {%0,%1,%2,%3};"
        : "+f"(d0), "+f"(d1), "+f"(d2), "+f"(d3)
        : "r"(a0), "r"(a1), "r"(a2), "r"(a3), "r"(b0), "r"(b1));
}

// ---------------- GroupNorm stats ----------------
__global__ void k_gnstats(const float* __restrict__ x){
    int b = blockIdx.y;
    const float4* xb = (const float4*)(x + (size_t)b*Cc*Ll);
    const int nt = (Cc*Ll)/4;
    float s = 0.f, q = 0.f;
    for (int i = blockIdx.x*blockDim.x + threadIdx.x; i < nt; i += gridDim.x*blockDim.x){
        float4 v = xb[i];
        s += v.x + v.y + v.z + v.w;
        q += v.x*v.x + v.y*v.y + v.z*v.z + v.w*v.w;
    }
    __shared__ float ss[256], qq[256];
    int t = threadIdx.x;
    ss[t] = s; qq[t] = q; __syncthreads();
    for (int o = 128; o > 0; o >>= 1){
        if (t < o){ ss[t] += ss[t+o]; qq[t] += qq[t+o]; }
        __syncthreads();
    }
    if (t == 0){
        g_part[b*128 + blockIdx.x] = ss[0];
        g_part[512 + b*128 + blockIdx.x] = qq[0];
    }
}

__global__ void k_gnfin(){
    int b = blockIdx.x, t = threadIdx.x;
    __shared__ float ss[128], qq[128];
    ss[t] = g_part[b*128 + t];
    qq[t] = g_part[512 + b*128 + t];
    __syncthreads();
    for (int o = 64; o > 0; o >>= 1){
        if (t < o){ ss[t] += ss[t+o]; qq[t] += qq[t+o]; }
        __syncthreads();
    }
    if (t == 0){ g_sum[b] = ss[0]; g_sumsq[b] = qq[0]; }
}

// ---------------- fused final weight ----------------
__global__ void k_wfuse(const float* __restrict__ P, const float* __restrict__ Wo){
    int idx = blockIdx.x*256 + threadIdx.x;
    if (idx >= Cc*Dd) return;
    int o = idx / Dd, d = idx % Dd;
    float acc = 0.f;
    for (int c = 0; c < Cc; c++) acc = fmaf(P[o*Cc + c], Wo[c*Dd + d], acc);
    g_wf[idx] = acc;
}

// ---------------- GEMM1: GN + in_proj, tf32 tensor-core ---------------------
// Block 128M x 128N, K-chunks of 16. 8 warps as 2(M)x4(N): warp = 64M x 32N.
// smem holds tf32 fragments in mma layout: one LDS.128 per A-frag, LDS.64 per B-frag.
__global__ __launch_bounds__(256) void k_inproj(const float* __restrict__ x,
        const float* __restrict__ gamma, const float* __restrict__ beta,
        const float* __restrict__ W){
    const int b  = blockIdx.z;
    const int m0 = blockIdx.x*128;
    const int n0 = blockIdx.y*128;
    const int tid = threadIdx.x;
    const int lane = tid & 31;
    const int w = tid >> 5;
    const int wm = w & 1;       // m-warp (0..1), 64 rows each
    const int wn = w >> 1;      // n-warp (0..3), 32 cols each

    // AsF: [s(2)][mt(8)][lane(32)][reg(4)]  = 2048 u32
    // BsF: [s(2)][nt(16)][lane(32)][reg(2)] = 2048 u32
    __shared__ unsigned AsF[2048];
    __shared__ unsigned BsF[2048];

    const float inv = 1.f/(float)(Cc*Ll);
    float mu   = g_sum[b]*inv;
    float var  = g_sumsq[b]*inv - mu*mu;
    float rstd = rsqrtf(var + 1e-5f);
    const float* xb = x + (size_t)b*Cc*Ll;

    float acc[4][4][4];   // [mt][nt][reg]
    #pragma unroll
    for (int i = 0; i < 4; i++)
        #pragma unroll
        for (int j = 0; j < 4; j++)
            #pragma unroll
            for (int r = 0; r < 4; r++) acc[i][j][r] = 0.f;

    for (int k0 = 0; k0 < Cc; k0 += 16){
        // ---- stage A (GN applied, cvt to tf32, fragment layout) ----
        #pragma unroll
        for (int i = 0; i < 2; i++){
            int lin = tid + i*256;          // 512 float4
            int k = lin >> 5, m4 = lin & 31;
            float4 v = *(const float4*)&xb[(size_t)(k0+k)*Ll + m0 + m4*4];
            float g = gamma[k0+k]*rstd, bt = beta[k0+k] - mu*g;
            float e[4] = { fmaf(v.x,g,bt), fmaf(v.y,g,bt), fmaf(v.z,g,bt), fmaf(v.w,g,bt) };
            int s = k >> 3, kk = k & 7;
            #pragma unroll
            for (int e4 = 0; e4 < 4; e4++){
                int m = m4*4 + e4;
                int mt = m >> 4, rr = m & 15;
                int ln = ((rr & 7) << 2) | (kk & 3);
                int rg = ((kk >> 2) << 1) | (rr >> 3);
                AsF[(((s*8 + mt)*32) + ln)*4 + rg] = cvt_tf32(e[e4]);
            }
        }
        // ---- stage B (W[n][k] row-major, fragment layout) ----
        #pragma unroll
        for (int i = 0; i < 2; i++){
            int lin = tid + i*256;          // 512 float4
            int n = lin & 127, kq = lin >> 7;
            float4 v = *(const float4*)&W[(size_t)(n0+n)*Cc + k0 + kq*4];
            float e[4] = {v.x, v.y, v.z, v.w};
            int nt = n >> 3, nn = n & 7;
            #pragma unroll
            for (int e4 = 0; e4 < 4; e4++){
                int k = kq*4 + e4;
                int s = k >> 3, kk = k & 7;
                int ln = (nn << 2) | (kk & 3);
                int rg = kk >> 2;
                BsF[(((s*16 + nt)*32) + ln)*2 + rg] = cvt_tf32(e[e4]);
            }
        }
        __syncthreads();
        // ---- consume: 2 k8-steps, 4x4 mma tiles per warp ----
        #pragma unroll
        for (int s = 0; s < 2; s++){
            unsigned a[4][4], bfr[4][2];
            #pragma unroll
            for (int i = 0; i < 4; i++){
                int mt = wm*4 + i;
                uint4 v = *(const uint4*)&AsF[(((s*8 + mt)*32) + lane)*4];
                a[i][0] = v.x; a[i][1] = v.y; a[i][2] = v.z; a[i][3] = v.w;
            }
            #pragma unroll
            for (int j = 0; j < 4; j++){
                int nt = wn*4 + j;
                uint2 v = *(const uint2*)&BsF[(((s*16 + nt)*32) + lane)*2];
                bfr[j][0] = v.x; bfr[j][1] = v.y;
            }
            #pragma unroll
            for (int i = 0; i < 4; i++)
                #pragma unroll
                for (int j = 0; j < 4; j++)
                    mma_tf32(acc[i][j][0], acc[i][j][1], acc[i][j][2], acc[i][j][3],
                             a[i][0], a[i][1], a[i][2], a[i][3], bfr[j][0], bfr[j][1]);
        }
        __syncthreads();
    }
    // ---- epilogue: c0,c1 at (row=g, col=2*tg), c2,c3 at (row=g+8) ----
    const int g  = lane >> 2;
    const int tg = lane & 3;
    #pragma unroll
    for (int i = 0; i < 4; i++){
        int mrow = wm*64 + i*16;
        #pragma unroll
        for (int j = 0; j < 4; j++){
            int ncol = wn*32 + j*8 + tg*2;
            #pragma unroll
            for (int half = 0; half < 2; half++){
                int m = m0 + mrow + g + half*8;
                float2 v = half ? make_float2(acc[i][j][2], acc[i][j][3])
                                : make_float2(acc[i][j][0], acc[i][j][1]);
                if (n0 < Dd){
                    int hh = m >> 6, ww = m & 63;
                    int lp = (hh & 1) ? ((hh << 6) + (63 - ww)) : m;
                    *(float2*)&g_u[((size_t)b*Ll + lp)*Dd + n0 + ncol] = v;
                } else {
                    *(float2*)&g_z[((size_t)b*Ll + m)*Dd + (n0 - Dd) + ncol] = v;
                }
            }
        }
    }
}

// ---------------- causal depthwise conv1d + SiLU ----------------
__global__ void k_conv(const float* __restrict__ cw, const float* __restrict__ cb){
    int idx = blockIdx.x*256 + threadIdx.x;
    if (idx >= BLD) return;
    int d = idx % Dd; int bl = idx / Dd; int l = bl % Ll; int b = bl / Ll;
    float acc = cb[d];
    #pragma unroll
    for (int j = 0; j < 4; j++){
        int ls = l - 3 + j;
        if (ls >= 0) acc = fmaf(g_u[((size_t)b*Ll + ls)*Dd + d], cw[d*4 + j], acc);
    }
    g_uc[idx] = acc / (1.f + __expf(-acc));
}

// ---------------- GEMM2: dbl = u_c @ x_proj_w^T ----------------
__global__ void k_dbl(const float* __restrict__ Wx){
    const int m0 = blockIdx.x*64;
    const int tid = threadIdx.x;
    const int tx = tid & 15, ty = tid >> 4;
    __shared__ float As[16][68];
    __shared__ float Bs[16][68];
    float acc[4][4] = {};
    for (int k0 = 0; k0 < Dd; k0 += 16){
        #pragma unroll
        for (int i = 0; i < 4; i++){
            int idx = tid + i*256;
            int m = idx >> 4, k = idx & 15;
            As[k][m] = g_uc[(size_t)(m0+m)*Dd + k0+k];
        }
        #pragma unroll
        for (int i = 0; i < 4; i++){
            int idx = tid + i*256;
            int n = idx >> 4, k = idx & 15;
            Bs[k][n] = (n < 44) ? Wx[(size_t)n*Dd + k0+k] : 0.f;
        }
        __syncthreads();
        #pragma unroll
        for (int kk = 0; kk < 16; kk++){
            float4 av = *(const float4*)&As[kk][ty*4];
            float4 bv = *(const float4*)&Bs[kk][tx*4];
            float a[4] = {av.x, av.y, av.z, av.w};
            float bb[4] = {bv.x, bv.y, bv.z, bv.w};
            #pragma unroll
            for (int i = 0; i < 4; i++)
                #pragma unroll
                for (int j = 0; j < 4; j++)
                    acc[i][j] = fmaf(a[i], bb[j], acc[i][j]);
        }
        __syncthreads();
    }
    #pragma unroll
    for (int i = 0; i < 4; i++){
        size_t row = m0 + ty*4 + i;
        #pragma unroll
        for (int j = 0; j < 4; j++){
            int e = tx*4 + j;
            if (e < 12)      g_dt[row*Rr + e]        = acc[i][j];
            else if (e < 28) g_Bm[row*Nst + (e-12)]  = acc[i][j];
            else if (e < 44) g_Cm[row*Nst + (e-28)]  = acc[i][j];
        }
    }
}

// ---------------- delta = softplus(dt @ dt_proj_w^T + b) -------------------
__global__ void k_delta(const float* __restrict__ dtw, const float* __restrict__ dtb){
    __shared__ float sw[Dd*13];
    for (int i = threadIdx.x; i < Dd*Rr; i += 256){
        int d = i / Rr, r = i % Rr;
        sw[d*13 + r] = dtw[i];
    }
    __syncthreads();
    for (int idx = blockIdx.x*256 + threadIdx.x; idx < BLD; idx += gridDim.x*256){
        int d = idx % Dd; size_t row = idx / Dd;
        const float* dtr = g_dt + row*Rr;
        float acc = dtb[d];
        #pragma unroll
        for (int r = 0; r < Rr; r++) acc = fmaf(dtr[r], sw[d*13 + r], acc);
        g_delta[idx] = fmaxf(acc, 0.f) + __logf(1.f + __expf(-fabsf(acc)));
    }
}

// ---------------- scan pass A ----------------
__global__ void k_scanA(const float* __restrict__ Alog){
    const int b = blockIdx.z;
    const int ch = blockIdx.y;
    const int dBase = blockIdx.x*16;
    const int tid = threadIdx.x;
    const int dl = tid >> 4;
    const int n  = tid & 15;
    const int d  = dBase + dl;
    float An = -__expf(Alog[d*Nst + n]);
    __shared__ float s_d[64][16], s_u[64][16], s_B[64][16];
    float h = 0.f, S = 0.f;
    const size_t base = (size_t)b*Ll + (size_t)ch*CHL;
    const float* pD = g_delta + base*Dd + dBase;
    const float* pU = g_uc    + base*Dd + dBase;
    const float* pB = g_Bm    + base*Nst;
    for (int l0 = 0; l0 < CHL; l0 += 64){
        #pragma unroll
        for (int i = 0; i < 4; i++){
            int idx = tid + i*256;
            int t = idx >> 4, c = idx & 15;
            s_d[t][c] = pD[(size_t)(l0+t)*Dd + c];
            s_u[t][c] = pU[(size_t)(l0+t)*Dd + c];
            s_B[t][c] = pB[(size_t)(l0+t)*Nst + c];
        }
        __syncthreads();
        #pragma unroll 8
        for (int t = 0; t < 64; t++){
            float dv = s_d[t][dl];
            float dA = __expf(dv * An);
            h = fmaf(dA, h, (dv*s_u[t][dl]) * s_B[t][n]);
            S += dv;
        }
        __syncthreads();
    }
    size_t o = (((size_t)b*NCH + ch)*Dd + d)*Nst + n;
    g_hend[o]  = h;
    g_aprod[o] = __expf(An * S);
}

// ---------------- scan pass B ----------------
__global__ void k_scanB(){
    int gid = blockIdx.x*256 + threadIdx.x;
    int b = gid / (Dd*Nst);
    int rem = gid % (Dd*Nst);
    float hin = 0.f;
    #pragma unroll
    for (int c = 0; c < NCH; c++){
        size_t o = ((size_t)(b*NCH + c))*(Dd*Nst) + rem;
        g_hin[o] = hin;
        hin = g_aprod[o]*hin + g_hend[o];
    }
}

// ---------------- scan pass C ----------------
__global__ void k_scanC(const float* __restrict__ Alog, const float* __restrict__ Dsk){
    const int b = blockIdx.z;
    const int ch = blockIdx.y;
    const int dBase = blockIdx.x*16;
    const int tid = threadIdx.x;
    const int dl = tid >> 4;
    const int n  = tid & 15;
    const int d  = dBase + dl;
    float An  = -__expf(Alog[d*Nst + n]);
    float dsk = Dsk[d];
    __shared__ float s_d[64][16], s_u[64][16], s_B[64][16], s_C[64][16];
    float h = g_hin[(((size_t)b*NCH + ch)*Dd + d)*Nst + n];
    const size_t base = (size_t)b*Ll + (size_t)ch*CHL;
    const float* pD = g_delta + base*Dd + dBase;
    const float* pU = g_uc    + base*Dd + dBase;
    const float* pB = g_Bm    + base*Nst;
    const float* pC = g_Cm    + base*Nst;
    float*       pY = g_y     + base*Dd + dBase;
    for (int l0 = 0; l0 < CHL; l0 += 64){
        #pragma unroll
        for (int i = 0; i < 4; i++){
            int idx = tid + i*256;
            int t = idx >> 4, c = idx & 15;
            s_d[t][c] = pD[(size_t)(l0+t)*Dd + c];
            s_u[t][c] = pU[(size_t)(l0+t)*Dd + c];
            s_B[t][c] = pB[(size_t)(l0+t)*Nst + c];
            s_C[t][c] = pC[(size_t)(l0+t)*Nst + c];
        }
        __syncthreads();
        #pragma unroll 4
        for (int t = 0; t < 64; t++){
            float dv = s_d[t][dl];
            float uv = s_u[t][dl];
            float dA = __expf(dv * An);
            h = fmaf(dA, h, (dv*uv) * s_B[t][n]);
            float p = h * s_C[t][n];
            p += __shfl_xor_sync(0xffffffffu, p, 8);
            p += __shfl_xor_sync(0xffffffffu, p, 4);
            p += __shfl_xor_sync(0xffffffffu, p, 2);
            p += __shfl_xor_sync(0xffffffffu, p, 1);
            if (n == 0) pY[(size_t)(l0+t)*Dd + dl] = p + uv*dsk;
        }
        __syncthreads();
    }
}

// ---------------- un-snake + gate ----------------
__global__ void k_gate(){
    int idx = blockIdx.x*256 + threadIdx.x;
    if (idx >= BLD) return;
    int d = idx % Dd; int bl = idx / Dd; int l = bl % Ll; int b = bl / Ll;
    int hh = l >> 6, ww = l & 63;
    int ls = (hh & 1) ? ((hh << 6) + (63 - ww)) : l;
    float yv = g_y[((size_t)b*Ll + ls)*Dd + d];
    float zv = g_z[idx];
    g_yg[idx] = yv * (zv / (1.f + __expf(-zv)));
}

// ---------------- depthwise 3x3 + residual ----------------
__global__ void k_le(const float* __restrict__ lw){
    int idx = blockIdx.x*256 + threadIdx.x;
    if (idx >= BLD) return;
    int d = idx % Dd; int bl = idx / Dd; int l = bl % Ll; int b = bl / Ll;
    int hh = l >> 6, ww = l & 63;
    float acc = g_yg[idx];
    #pragma unroll
    for (int dh = -1; dh <= 1; dh++){
        int h2 = hh + dh;
        if ((unsigned)h2 >= (unsigned)Hh) continue;
        #pragma unroll
        for (int dw = -1; dw <= 1; dw++){
            int w2 = ww + dw;
            if ((unsigned)w2 >= (unsigned)Wd) continue;
            acc = fmaf(g_yg[((size_t)b*Ll + (h2<<6) + w2)*Dd + d],
                       lw[d*9 + (dh+1)*3 + (dw+1)], acc);
        }
    }
    g_y2[idx] = acc;
}

// ---------------- GEMM3: out (128x64, 8x4/thread) ----------------
__global__ __launch_bounds__(256) void k_out(float* __restrict__ out){
    const int m0 = blockIdx.x*128;
    const int n0 = blockIdx.y*64;
    const int tid = threadIdx.x;
    const int tx = tid & 15, ty = tid >> 4;
    __shared__ float As[16][128];
    __shared__ float Bs[16][64];
    float acc[8][4] = {};
    for (int k0 = 0; k0 < Dd; k0 += 16){
        #pragma unroll
        for (int i = 0; i < 2; i++){
            int lin = tid + i*256;
            int m = lin & 127, kq = lin >> 7;
            float4 v = *(const float4*)&g_y2[(size_t)(m0+m)*Dd + k0 + kq*4];
            As[kq*4+0][m] = v.x; As[kq*4+1][m] = v.y;
            As[kq*4+2][m] = v.z; As[kq*4+3][m] = v.w;
        }
        {
            int n = tid & 63, kq = tid >> 6;
            float4 v = *(const float4*)&g_wf[(size_t)(n0+n)*Dd + k0 + kq*4];
            Bs[kq*4+0][n] = v.x; Bs[kq*4+1][n] = v.y;
            Bs[kq*4+2][n] = v.z; Bs[kq*4+3][n] = v.w;
        }
        __syncthreads();
        #pragma unroll
        for (int kk = 0; kk < 16; kk++){
            float a[8], bb[4];
            *(float4*)&a[0]  = *(const float4*)&As[kk][ty*8];
            *(float4*)&a[4]  = *(const float4*)&As[kk][ty*8+4];
            *(float4*)&bb[0] = *(const float4*)&Bs[kk][tx*4];
            #pragma unroll
            for (int i = 0; i < 8; i++)
                #pragma unroll
                for (int j = 0; j < 4; j++)
                    acc[i][j] = fmaf(a[i], bb[j], acc[i][j]);
        }
        __syncthreads();
    }
    int b = m0 >> 12;
    int lbase = (m0 & 4095) + ty*8;
    #pragma unroll
    for (int j = 0; j < 4; j++){
        int o = n0 + tx*4 + j;
        float* p = &out[((size_t)b*Cc + o)*Ll + lbase];
        *(float4*)p     = make_float4(acc[0][j], acc[1][j], acc[2][j], acc[3][j]);
        *(float4*)(p+4) = make_float4(acc[4][j], acc[5][j], acc[6][j], acc[7][j]);
    }
}

extern "C" void kernel_launch(void* const* d_in, const int* in_sizes, int n_in,
                              void* d_out, int out_size){
    const float* x          = (const float*)d_in[0];
    const float* gn_gamma   = (const float*)d_in[1];
    const float* gn_beta    = (const float*)d_in[2];
    const float* in_proj_w  = (const float*)d_in[3];
    const float* conv1d_w   = (const float*)d_in[4];
    const float* conv1d_b   = (const float*)d_in[5];
    const float* x_proj_w   = (const float*)d_in[6];
    const float* dt_proj_w  = (const float*)d_in[7];
    const float* dt_proj_b  = (const float*)d_in[8];
    const float* A_log      = (const float*)d_in[9];
    const float* Dskip      = (const float*)d_in[10];
    const float* le_w       = (const float*)d_in[11];
    const float* out_proj_w = (const float*)d_in[12];
    const float* proj_out_w = (const float*)d_in[13];
    float* out = (float*)d_out;

    k_gnstats<<<dim3(128, Bb), 256>>>(x);
    k_gnfin<<<Bb, 128>>>();
    k_wfuse<<<(Cc*Dd + 255)/256, 256>>>(proj_out_w, out_proj_w);
    k_inproj<<<dim3(Ll/128, 768/128, Bb), 256>>>(x, gn_gamma, gn_beta, in_proj_w);
    k_conv<<<BLD/256, 256>>>(conv1d_w, conv1d_b);
    k_dbl<<<(Bb*Ll)/64, 256>>>(x_proj_w);
    k_delta<<<2048, 256>>>(dt_proj_w, dt_proj_b);
    k_scanA<<<dim3(Dd/16, NCH, Bb), 256>>>(A_log);
    k_scanB<<<(Bb*Dd*Nst)/256, 256>>>();
    k_scanC<<<dim3(Dd/16, NCH, Bb), 256>>>(A_log, Dskip);
    k_gate<<<BLD/256, 256>>>();
    k_le<<<BLD/256, 256>>>(le_w);
    k_out<<<dim3((Bb*Ll)/128, Cc/64), 256>>>(out);
}

// round 5
// speedup vs baseline: 1.9460x; 1.1869x over previous
#include <cuda_runtime.h>
#include <cuda_bf16.h>
#include <math.h>

#define Bb 4
#define Cc 192
#define Hh 64
#define Wd 64
#define Ll 4096
#define Dd 384
#define Nst 16
#define Rr 12
#define BLD (Bb*Ll*Dd)
#define NCH 16
#define CHL 256

// scratch
__device__ float g_part[2*128*Bb];
__device__ float g_sum[Bb], g_sumsq[Bb];
__device__ float g_u[BLD];      // snake order
__device__ float g_z[BLD];      // raster order
__device__ float g_uc[BLD];     // snake order
__device__ float g_delta[BLD];  // snake order
__device__ float g_y[BLD];      // snake order
__device__ float g_yg[BLD];     // raster order
__device__ float g_y2[BLD];     // raster order
__device__ float g_dt[Bb*Ll*Rr];
__device__ float g_Bm[Bb*Ll*Nst];
__device__ float g_Cm[Bb*Ll*Nst];
__device__ float g_wf[Cc*Dd];
__device__ float g_hend[Bb*NCH*Dd*Nst];
__device__ float g_aprod[Bb*NCH*Dd*Nst];
__device__ float g_hin[Bb*NCH*Dd*Nst];

__device__ __forceinline__ unsigned cvt_tf32(float v){
    unsigned r; asm("cvt.rna.tf32.f32 %0, %1;" : "=r"(r) : "f"(v)); return r;
}
__device__ __forceinline__ void mma_tf32(float &d0, float &d1, float &d2, float &d3,
        unsigned a0, unsigned a1, unsigned a2, unsigned a3, unsigned b0, unsigned b1){
    asm("mma.sync.aligned.m16n8k8.row.col.f32.tf32.tf32.f32 "
        "{%0,%1,%2,%3}, {%4,%5,%6,%7}, {%8,%9}, {%0,%1,%2,%3};"
        : "+f"(d0), "+f"(d1), "+f"(d2), "+f"(d3)
        : "r"(a0), "r"(a1), "r"(a2), "r"(a3), "r"(b0), "r"(b1));
}

// ---------------- GroupNorm stats ----------------
__global__ void k_gnstats(const float* __restrict__ x){
    int b = blockIdx.y;
    const float4* xb = (const float4*)(x + (size_t)b*Cc*Ll);
    const int nt = (Cc*Ll)/4;
    float s = 0.f, q = 0.f;
    for (int i = blockIdx.x*blockDim.x + threadIdx.x; i < nt; i += gridDim.x*blockDim.x){
        float4 v = xb[i];
        s += v.x + v.y + v.z + v.w;
        q += v.x*v.x + v.y*v.y + v.z*v.z + v.w*v.w;
    }
    __shared__ float ss[256], qq[256];
    int t = threadIdx.x;
    ss[t] = s; qq[t] = q; __syncthreads();
    for (int o = 128; o > 0; o >>= 1){
        if (t < o){ ss[t] += ss[t+o]; qq[t] += qq[t+o]; }
        __syncthreads();
    }
    if (t == 0){
        g_part[b*128 + blockIdx.x] = ss[0];
        g_part[512 + b*128 + blockIdx.x] = qq[0];
    }
}

__global__ void k_gnfin(){
    int b = blockIdx.x, t = threadIdx.x;
    __shared__ float ss[128], qq[128];
    ss[t] = g_part[b*128 + t];
    qq[t] = g_part[512 + b*128 + t];
    __syncthreads();
    for (int o = 64; o > 0; o >>= 1){
        if (t < o){ ss[t] += ss[t+o]; qq[t] += qq[t+o]; }
        __syncthreads();
    }
    if (t == 0){ g_sum[b] = ss[0]; g_sumsq[b] = qq[0]; }
}

// ---------------- fused final weight ----------------
__global__ void k_wfuse(const float* __restrict__ P, const float* __restrict__ Wo){
    int idx = blockIdx.x*256 + threadIdx.x;
    if (idx >= Cc*Dd) return;
    int o = idx / Dd, d = idx % Dd;
    float acc = 0.f;
    for (int c = 0; c < Cc; c++) acc = fmaf(P[o*Cc + c], Wo[c*Dd + d], acc);
    g_wf[idx] = acc;
}

// ---------------- GEMM1: GN + in_proj, tf32, bank-exact staging -------------
// Block 128M x 128N, K-chunk 32. 8 warps = 2(M)x4(N); warp = 64M x 32N.
// As: [k][m] stride 136 (136%32==8 -> frag banks 8*tg+g distinct)
// Bs: [n][k] stride 36  (36%32==4  -> frag banks 4*gn+tg distinct)
#define PSA 136
#define PSB 36
__global__ __launch_bounds__(256) void k_inproj(const float* __restrict__ x,
        const float* __restrict__ gamma, const float* __restrict__ beta,
        const float* __restrict__ W){
    const int b  = blockIdx.z;
    const int m0 = blockIdx.x*128;
    const int n0 = blockIdx.y*128;
    const int tid = threadIdx.x;
    const int lane = tid & 31;
    const int w = tid >> 5;
    const int wm = w & 1;
    const int wn = w >> 1;
    const int g  = lane >> 2;
    const int tg = lane & 3;

    __shared__ unsigned As[32*PSA];   // 17408 B
    __shared__ unsigned Bs[128*PSB];  // 18432 B

    const float inv = 1.f/(float)(Cc*Ll);
    float mu   = g_sum[b]*inv;
    float var  = g_sumsq[b]*inv - mu*mu;
    float rstd = rsqrtf(var + 1e-5f);
    const float* xb = x + (size_t)b*Cc*Ll;

    float acc[4][4][4];
    #pragma unroll
    for (int i = 0; i < 4; i++)
        #pragma unroll
        for (int j = 0; j < 4; j++)
            #pragma unroll
            for (int r = 0; r < 4; r++) acc[i][j][r] = 0.f;

    for (int k0 = 0; k0 < Cc; k0 += 32){
        // stage A: [k][m], coalesced gmem, STS.128
        #pragma unroll
        for (int i = 0; i < 4; i++){
            int lin = tid + i*256;           // 1024 float4 slots
            int k = lin >> 5, m4 = lin & 31;
            float4 v = *(const float4*)&xb[(size_t)(k0+k)*Ll + m0 + m4*4];
            float gg = gamma[k0+k]*rstd, bt = beta[k0+k] - mu*gg;
            uint4 o;
            o.x = cvt_tf32(fmaf(v.x, gg, bt));
            o.y = cvt_tf32(fmaf(v.y, gg, bt));
            o.z = cvt_tf32(fmaf(v.z, gg, bt));
            o.w = cvt_tf32(fmaf(v.w, gg, bt));
            *(uint4*)&As[k*PSA + m4*4] = o;
        }
        // stage B: [n][k], STS.128
        #pragma unroll
        for (int i = 0; i < 4; i++){
            int lin = tid + i*256;           // 1024 float4 slots
            int kq = lin & 7, n = lin >> 3;
            float4 v = *(const float4*)&W[(size_t)(n0+n)*Cc + k0 + kq*4];
            uint4 o;
            o.x = cvt_tf32(v.x); o.y = cvt_tf32(v.y);
            o.z = cvt_tf32(v.z); o.w = cvt_tf32(v.w);
            *(uint4*)&Bs[n*PSB + kq*4] = o;
        }
        __syncthreads();
        #pragma unroll
        for (int s = 0; s < 4; s++){
            unsigned a[4][4], bf[4][2];
            int ka = s*8 + tg;
            #pragma unroll
            for (int i = 0; i < 4; i++){
                int mb = (wm*4 + i)*16 + g;
                a[i][0] = As[ka*PSA + mb];
                a[i][1] = As[ka*PSA + mb + 8];
                a[i][2] = As[(ka+4)*PSA + mb];
                a[i][3] = As[(ka+4)*PSA + mb + 8];
            }
            #pragma unroll
            for (int j = 0; j < 4; j++){
                int nb = ((wn*4 + j)*8 + g)*PSB + s*8 + tg;
                bf[j][0] = Bs[nb];
                bf[j][1] = Bs[nb + 4];
            }
            #pragma unroll
            for (int i = 0; i < 4; i++)
                #pragma unroll
                for (int j = 0; j < 4; j++)
                    mma_tf32(acc[i][j][0], acc[i][j][1], acc[i][j][2], acc[i][j][3],
                             a[i][0], a[i][1], a[i][2], a[i][3], bf[j][0], bf[j][1]);
        }
        __syncthreads();
    }
    #pragma unroll
    for (int i = 0; i < 4; i++){
        int mrow = wm*64 + i*16;
        #pragma unroll
        for (int j = 0; j < 4; j++){
            int ncol = wn*32 + j*8 + tg*2;
            #pragma unroll
            for (int half = 0; half < 2; half++){
                int m = m0 + mrow + g + half*8;
                float2 v = half ? make_float2(acc[i][j][2], acc[i][j][3])
                                : make_float2(acc[i][j][0], acc[i][j][1]);
                if (n0 < Dd){
                    int hh = m >> 6, ww = m & 63;
                    int lp = (hh & 1) ? ((hh << 6) + (63 - ww)) : m;
                    *(float2*)&g_u[((size_t)b*Ll + lp)*Dd + n0 + ncol] = v;
                } else {
                    *(float2*)&g_z[((size_t)b*Ll + m)*Dd + (n0 - Dd) + ncol] = v;
                }
            }
        }
    }
}

// ---------------- causal depthwise conv1d + SiLU ----------------
__global__ void k_conv(const float* __restrict__ cw, const float* __restrict__ cb){
    int idx = blockIdx.x*256 + threadIdx.x;
    if (idx >= BLD) return;
    int d = idx % Dd; int bl = idx / Dd; int l = bl % Ll; int b = bl / Ll;
    float acc = cb[d];
    #pragma unroll
    for (int j = 0; j < 4; j++){
        int ls = l - 3 + j;
        if (ls >= 0) acc = fmaf(g_u[((size_t)b*Ll + ls)*Dd + d], cw[d*4 + j], acc);
    }
    g_uc[idx] = acc / (1.f + __expf(-acc));
}

// ---------------- GEMM2: dbl = u_c @ x_proj_w^T ----------------
__global__ void k_dbl(const float* __restrict__ Wx){
    const int m0 = blockIdx.x*64;
    const int tid = threadIdx.x;
    const int tx = tid & 15, ty = tid >> 4;
    __shared__ float As2[16][68];
    __shared__ float Bs2[16][68];
    float acc[4][4] = {};
    for (int k0 = 0; k0 < Dd; k0 += 16){
        #pragma unroll
        for (int i = 0; i < 4; i++){
            int idx = tid + i*256;
            int m = idx >> 4, k = idx & 15;
            As2[k][m] = g_uc[(size_t)(m0+m)*Dd + k0+k];
        }
        #pragma unroll
        for (int i = 0; i < 4; i++){
            int idx = tid + i*256;
            int n = idx >> 4, k = idx & 15;
            Bs2[k][n] = (n < 44) ? Wx[(size_t)n*Dd + k0+k] : 0.f;
        }
        __syncthreads();
        #pragma unroll
        for (int kk = 0; kk < 16; kk++){
            float4 av = *(const float4*)&As2[kk][ty*4];
            float4 bv = *(const float4*)&Bs2[kk][tx*4];
            float a[4] = {av.x, av.y, av.z, av.w};
            float bb[4] = {bv.x, bv.y, bv.z, bv.w};
            #pragma unroll
            for (int i = 0; i < 4; i++)
                #pragma unroll
                for (int j = 0; j < 4; j++)
                    acc[i][j] = fmaf(a[i], bb[j], acc[i][j]);
        }
        __syncthreads();
    }
    #pragma unroll
    for (int i = 0; i < 4; i++){
        size_t row = m0 + ty*4 + i;
        #pragma unroll
        for (int j = 0; j < 4; j++){
            int e = tx*4 + j;
            if (e < 12)      g_dt[row*Rr + e]        = acc[i][j];
            else if (e < 28) g_Bm[row*Nst + (e-12)]  = acc[i][j];
            else if (e < 44) g_Cm[row*Nst + (e-28)]  = acc[i][j];
        }
    }
}

// ---------------- delta = softplus(dt @ dt_proj_w^T + b) -------------------
__global__ void k_delta(const float* __restrict__ dtw, const float* __restrict__ dtb){
    __shared__ float sw[Dd*13];
    for (int i = threadIdx.x; i < Dd*Rr; i += 256){
        int d = i / Rr, r = i % Rr;
        sw[d*13 + r] = dtw[i];
    }
    __syncthreads();
    for (int idx = blockIdx.x*256 + threadIdx.x; idx < BLD; idx += gridDim.x*256){
        int d = idx % Dd; size_t row = idx / Dd;
        const float* dtr = g_dt + row*Rr;
        float acc = dtb[d];
        #pragma unroll
        for (int r = 0; r < Rr; r++) acc = fmaf(dtr[r], sw[d*13 + r], acc);
        g_delta[idx] = fmaxf(acc, 0.f) + __logf(1.f + __expf(-fabsf(acc)));
    }
}

// ---------------- scan pass A ----------------
__global__ void k_scanA(const float* __restrict__ Alog){
    const int b = blockIdx.z;
    const int ch = blockIdx.y;
    const int dBase = blockIdx.x*16;
    const int tid = threadIdx.x;
    const int dl = tid >> 4;
    const int n  = tid & 15;
    const int d  = dBase + dl;
    float An = -__expf(Alog[d*Nst + n]);
    __shared__ float s_d[64][16], s_u[64][16], s_B[64][16];
    float h = 0.f, S = 0.f;
    const size_t base = (size_t)b*Ll + (size_t)ch*CHL;
    const float* pD = g_delta + base*Dd + dBase;
    const float* pU = g_uc    + base*Dd + dBase;
    const float* pB = g_Bm    + base*Nst;
    for (int l0 = 0; l0 < CHL; l0 += 64){
        #pragma unroll
        for (int i = 0; i < 4; i++){
            int idx = tid + i*256;
            int t = idx >> 4, c = idx & 15;
            s_d[t][c] = pD[(size_t)(l0+t)*Dd + c];
            s_u[t][c] = pU[(size_t)(l0+t)*Dd + c];
            s_B[t][c] = pB[(size_t)(l0+t)*Nst + c];
        }
        __syncthreads();
        #pragma unroll 8
        for (int t = 0; t < 64; t++){
            float dv = s_d[t][dl];
            float dA = __expf(dv * An);
            h = fmaf(dA, h, (dv*s_u[t][dl]) * s_B[t][n]);
            S += dv;
        }
        __syncthreads();
    }
    size_t o = (((size_t)b*NCH + ch)*Dd + d)*Nst + n;
    g_hend[o]  = h;
    g_aprod[o] = __expf(An * S);
}

// ---------------- scan pass B ----------------
__global__ void k_scanB(){
    int gid = blockIdx.x*256 + threadIdx.x;
    int b = gid / (Dd*Nst);
    int rem = gid % (Dd*Nst);
    float hin = 0.f;
    #pragma unroll
    for (int c = 0; c < NCH; c++){
        size_t o = ((size_t)(b*NCH + c))*(Dd*Nst) + rem;
        g_hin[o] = hin;
        hin = g_aprod[o]*hin + g_hend[o];
    }
}

// ---------------- scan pass C ----------------
__global__ void k_scanC(const float* __restrict__ Alog, const float* __restrict__ Dsk){
    const int b = blockIdx.z;
    const int ch = blockIdx.y;
    const int dBase = blockIdx.x*16;
    const int tid = threadIdx.x;
    const int dl = tid >> 4;
    const int n  = tid & 15;
    const int d  = dBase + dl;
    float An  = -__expf(Alog[d*Nst + n]);
    float dsk = Dsk[d];
    __shared__ float s_d[64][16], s_u[64][16], s_B[64][16], s_C[64][16];
    float h = g_hin[(((size_t)b*NCH + ch)*Dd + d)*Nst + n];
    const size_t base = (size_t)b*Ll + (size_t)ch*CHL;
    const float* pD = g_delta + base*Dd + dBase;
    const float* pU = g_uc    + base*Dd + dBase;
    const float* pB = g_Bm    + base*Nst;
    const float* pC = g_Cm    + base*Nst;
    float*       pY = g_y     + base*Dd + dBase;
    for (int l0 = 0; l0 < CHL; l0 += 64){
        #pragma unroll
        for (int i = 0; i < 4; i++){
            int idx = tid + i*256;
            int t = idx >> 4, c = idx & 15;
            s_d[t][c] = pD[(size_t)(l0+t)*Dd + c];
            s_u[t][c] = pU[(size_t)(l0+t)*Dd + c];
            s_B[t][c] = pB[(size_t)(l0+t)*Nst + c];
            s_C[t][c] = pC[(size_t)(l0+t)*Nst + c];
        }
        __syncthreads();
        #pragma unroll 4
        for (int t = 0; t < 64; t++){
            float dv = s_d[t][dl];
            float uv = s_u[t][dl];
            float dA = __expf(dv * An);
            h = fmaf(dA, h, (dv*uv) * s_B[t][n]);
            float p = h * s_C[t][n];
            p += __shfl_xor_sync(0xffffffffu, p, 8);
            p += __shfl_xor_sync(0xffffffffu, p, 4);
            p += __shfl_xor_sync(0xffffffffu, p, 2);
            p += __shfl_xor_sync(0xffffffffu, p, 1);
            if (n == 0) pY[(size_t)(l0+t)*Dd + dl] = p + uv*dsk;
        }
        __syncthreads();
    }
}

// ---------------- un-snake + gate ----------------
__global__ void k_gate(){
    int idx = blockIdx.x*256 + threadIdx.x;
    if (idx >= BLD) return;
    int d = idx % Dd; int bl = idx / Dd; int l = bl % Ll; int b = bl / Ll;
    int hh = l >> 6, ww = l & 63;
    int ls = (hh & 1) ? ((hh << 6) + (63 - ww)) : l;
    float yv = g_y[((size_t)b*Ll + ls)*Dd + d];
    float zv = g_z[idx];
    g_yg[idx] = yv * (zv / (1.f + __expf(-zv)));
}

// ---------------- depthwise 3x3 + residual ----------------
__global__ void k_le(const float* __restrict__ lw){
    int idx = blockIdx.x*256 + threadIdx.x;
    if (idx >= BLD) return;
    int d = idx % Dd; int bl = idx / Dd; int l = bl % Ll; int b = bl / Ll;
    int hh = l >> 6, ww = l & 63;
    float acc = g_yg[idx];
    #pragma unroll
    for (int dh = -1; dh <= 1; dh++){
        int h2 = hh + dh;
        if ((unsigned)h2 >= (unsigned)Hh) continue;
        #pragma unroll
        for (int dw = -1; dw <= 1; dw++){
            int w2 = ww + dw;
            if ((unsigned)w2 >= (unsigned)Wd) continue;
            acc = fmaf(g_yg[((size_t)b*Ll + (h2<<6) + w2)*Dd + d],
                       lw[d*9 + (dh+1)*3 + (dw+1)], acc);
        }
    }
    g_y2[idx] = acc;
}

// ---------------- GEMM3: out, 3xTF32 (hi/lo split) --------------------------
// Block 128M x 64N, K-chunk 16. 8 warps = 4(M)x2(N); warp = 32M x 32N.
// As/Bs row-major [m][k]/[n][k], stride 20 (20%32: 20g+tg distinct banks).
#define PSO 20
__global__ __launch_bounds__(256) void k_out(float* __restrict__ out){
    const int m0 = blockIdx.x*128;
    const int n0 = blockIdx.y*64;
    const int tid = threadIdx.x;
    const int lane = tid & 31;
    const int w = tid >> 5;
    const int wm = w & 3;
    const int wn = w >> 2;
    const int g  = lane >> 2;
    const int tg = lane & 3;

    __shared__ unsigned AsH[128*PSO], AsL[128*PSO];  // 2*10240 B
    __shared__ unsigned BsH[64*PSO],  BsL[64*PSO];   // 2*5120 B

    float acc[2][4][4];
    #pragma unroll
    for (int i = 0; i < 2; i++)
        #pragma unroll
        for (int j = 0; j < 4; j++)
            #pragma unroll
            for (int r = 0; r < 4; r++) acc[i][j][r] = 0.f;

    for (int k0 = 0; k0 < Dd; k0 += 16){
        // stage A: 128m x 16k
        #pragma unroll
        for (int i = 0; i < 2; i++){
            int lin = tid + i*256;           // 512 float4 slots
            int kq = lin & 3, m = lin >> 2;
            float4 v = *(const float4*)&g_y2[(size_t)(m0+m)*Dd + k0 + kq*4];
            uint4 hi, lo;
            hi.x = cvt_tf32(v.x); lo.x = cvt_tf32(v.x - __uint_as_float(hi.x));
            hi.y = cvt_tf32(v.y); lo.y = cvt_tf32(v.y - __uint_as_float(hi.y));
            hi.z = cvt_tf32(v.z); lo.z = cvt_tf32(v.z - __uint_as_float(hi.z));
            hi.w = cvt_tf32(v.w); lo.w = cvt_tf32(v.w - __uint_as_float(hi.w));
            *(uint4*)&AsH[m*PSO + kq*4] = hi;
            *(uint4*)&AsL[m*PSO + kq*4] = lo;
        }
        // stage B: 64n x 16k
        if (tid < 256){
            int lin = tid;                    // 256 float4 slots
            int kq = lin & 3, n = lin >> 2;
            float4 v = *(const float4*)&g_wf[(size_t)(n0+n)*Dd + k0 + kq*4];
            uint4 hi, lo;
            hi.x = cvt_tf32(v.x); lo.x = cvt_tf32(v.x - __uint_as_float(hi.x));
            hi.y = cvt_tf32(v.y); lo.y = cvt_tf32(v.y - __uint_as_float(hi.y));
            hi.z = cvt_tf32(v.z); lo.z = cvt_tf32(v.z - __uint_as_float(hi.z));
            hi.w = cvt_tf32(v.w); lo.w = cvt_tf32(v.w - __uint_as_float(hi.w));
            *(uint4*)&BsH[n*PSO + kq*4] = hi;
            *(uint4*)&BsL[n*PSO + kq*4] = lo;
        }
        __syncthreads();
        #pragma unroll
        for (int s = 0; s < 2; s++){
            unsigned aH[2][4], aL[2][4], bH[4][2], bL[4][2];
            int kb = s*8 + tg;
            #pragma unroll
            for (int i = 0; i < 2; i++){
                int mb = (wm*2 + i)*16 + g;
                aH[i][0] = AsH[mb*PSO + kb];       aL[i][0] = AsL[mb*PSO + kb];
                aH[i][1] = AsH[(mb+8)*PSO + kb];   aL[i][1] = AsL[(mb+8)*PSO + kb];
                aH[i][2] = AsH[mb*PSO + kb+4];     aL[i][2] = AsL[mb*PSO + kb+4];
                aH[i][3] = AsH[(mb+8)*PSO + kb+4]; aL[i][3] = AsL[(mb+8)*PSO + kb+4];
            }
            #pragma unroll
            for (int j = 0; j < 4; j++){
                int nb = (wn*4 + j)*8 + g;
                bH[j][0] = BsH[nb*PSO + kb];   bL[j][0] = BsL[nb*PSO + kb];
                bH[j][1] = BsH[nb*PSO + kb+4]; bL[j][1] = BsL[nb*PSO + kb+4];
            }
            #pragma unroll
            for (int i = 0; i < 2; i++)
                #pragma unroll
                for (int j = 0; j < 4; j++){
                    mma_tf32(acc[i][j][0], acc[i][j][1], acc[i][j][2], acc[i][j][3],
                             aH[i][0], aH[i][1], aH[i][2], aH[i][3], bL[j][0], bL[j][1]);
                    mma_tf32(acc[i][j][0], acc[i][j][1], acc[i][j][2], acc[i][j][3],
                             aL[i][0], aL[i][1], aL[i][2], aL[i][3], bH[j][0], bH[j][1]);
                    mma_tf32(acc[i][j][0], acc[i][j][1], acc[i][j][2], acc[i][j][3],
                             aH[i][0], aH[i][1], aH[i][2], aH[i][3], bH[j][0], bH[j][1]);
                }
        }
        __syncthreads();
    }
    int b = m0 >> 12;
    int lb = m0 & 4095;
    #pragma unroll
    for (int i = 0; i < 2; i++){
        int l = lb + wm*32 + i*16 + g;
        #pragma unroll
        for (int j = 0; j < 4; j++){
            int o = n0 + wn*32 + j*8 + tg*2;
            out[((size_t)b*Cc + o  )*Ll + l]     = acc[i][j][0];
            out[((size_t)b*Cc + o+1)*Ll + l]     = acc[i][j][1];
            out[((size_t)b*Cc + o  )*Ll + l + 8] = acc[i][j][2];
            out[((size_t)b*Cc + o+1)*Ll + l + 8] = acc[i][j][3];
        }
    }
}

extern "C" void kernel_launch(void* const* d_in, const int* in_sizes, int n_in,
                              void* d_out, int out_size){
    const float* x          = (const float*)d_in[0];
    const float* gn_gamma   = (const float*)d_in[1];
    const float* gn_beta    = (const float*)d_in[2];
    const float* in_proj_w  = (const float*)d_in[3];
    const float* conv1d_w   = (const float*)d_in[4];
    const float* conv1d_b   = (const float*)d_in[5];
    const float* x_proj_w   = (const float*)d_in[6];
    const float* dt_proj_w  = (const float*)d_in[7];
    const float* dt_proj_b  = (const float*)d_in[8];
    const float* A_log      = (const float*)d_in[9];
    const float* Dskip      = (const float*)d_in[10];
    const float* le_w       = (const float*)d_in[11];
    const float* out_proj_w = (const float*)d_in[12];
    const float* proj_out_w = (const float*)d_in[13];
    float* out = (float*)d_out;

    k_gnstats<<<dim3(128, Bb), 256>>>(x);
    k_gnfin<<<Bb, 128>>>();
    k_wfuse<<<(Cc*Dd + 255)/256, 256>>>(proj_out_w, out_proj_w);
    k_inproj<<<dim3(Ll/128, 768/128, Bb), 256>>>(x, gn_gamma, gn_beta, in_proj_w);
    k_conv<<<BLD/256, 256>>>(conv1d_w, conv1d_b);
    k_dbl<<<(Bb*Ll)/64, 256>>>(x_proj_w);
    k_delta<<<2048, 256>>>(dt_proj_w, dt_proj_b);
    k_scanA<<<dim3(Dd/16, NCH, Bb), 256>>>(A_log);
    k_scanB<<<(Bb*Dd*Nst)/256, 256>>>();
    k_scanC<<<dim3(Dd/16, NCH, Bb), 256>>>(A_log, Dskip);
    k_gate<<<BLD/256, 256>>>();
    k_le<<<BLD/256, 256>>>(le_w);
    k_out<<<dim3((Bb*Ll)/128, Cc/64), 256>>>(out);
}